// round 7
// baseline (speedup 1.0000x reference)
#include <cuda_runtime.h>

// Problem constants (fixed shapes for this problem instance)
#define NN 100000   // nodes
#define NE 800000   // edges
#define VC 256      // vocab
#define DM 256      // node dim == hidden == vocab
#define NM 10000    // masked outputs

#define SB 512
#define NSB ((NN + SB - 1) / SB)   // 196 scan blocks

// ---------------- scratch (device globals; no allocation allowed) ----------
__device__ int   g_deg[NN];
__device__ int   g_cur[NN];     // seeded to CSR offset; atomic bump at place
__device__ int   g_bsum[NSB];
__device__ int   g_masked[NN];
__device__ int   g_needed[NN];
__device__ __align__(16) int4  g_nd[NN];           // {x, dinv_bits, off, cnt}
__device__ __align__(16) float g_EW[VC * DM];      // emb @ W1, fp32 (256 KB)
__device__ __align__(16) float g_out1[NN * DM];    // layer-1 pre-activation (102 MB)
__device__ __align__(16) float g_aggc[NM * DM];    // layer-2 aggregate, compact (10 MB)
__device__ __align__(16) int4  g_edge[NE];         // {x[src], src, coef_bits, 0}

// ---------------- kernels ---------------------------------------------------

__global__ void k_init(void) {
    int i = blockIdx.x * blockDim.x + threadIdx.x;
    if (i < NN) { g_deg[i] = 1; g_masked[i] = 0; g_needed[i] = 0; }
}

// fused: degree count (first NE threads) + mask marking (next NM threads)
__global__ void k_degmark(const int* __restrict__ ei, const int* __restrict__ mask) {
    int t = blockIdx.x * blockDim.x + threadIdx.x;
    if (t < NE) {
        atomicAdd(&g_deg[ei[NE + t]], 1);
    } else if (t < NE + NM) {
        int n = mask[t - NE];
        g_masked[n] = 1;
        g_needed[n] = 1;          // self term of layer-2 reads out1[node]
    }
}

// ---- exclusive prefix scan of (deg-1) -> CSR row offsets -------------------
__global__ void k_scanA(void) {
    __shared__ int s[SB];
    int i = blockIdx.x * SB + threadIdx.x;
    int v = (i < NN) ? (g_deg[i] - 1) : 0;
    s[threadIdx.x] = v;
    __syncthreads();
    for (int o = 1; o < SB; o <<= 1) {
        int t = (threadIdx.x >= o) ? s[threadIdx.x - o] : 0;
        __syncthreads();
        s[threadIdx.x] += t;
        __syncthreads();
    }
    int inc = s[threadIdx.x];
    if (i < NN) g_cur[i] = inc - v;                 // exclusive (pre-bsum)
    if (threadIdx.x == SB - 1) g_bsum[blockIdx.x] = inc;
}

__global__ void k_scanB(void) {   // one block of 256 >= NSB
    __shared__ int s[256];
    int t = threadIdx.x;
    int v = (t < NSB) ? g_bsum[t] : 0;
    s[t] = v;
    __syncthreads();
    for (int o = 1; o < 256; o <<= 1) {
        int u = (t >= o) ? s[t - o] : 0;
        __syncthreads();
        s[t] += u;
        __syncthreads();
    }
    if (t < NSB) g_bsum[t] = s[t] - v;              // exclusive
}

// finalize offsets + build node record {x, dinv, off, cnt}; seed g_cur = off
__global__ void k_scanC(const int* __restrict__ x) {
    int i = blockIdx.x * SB + threadIdx.x;
    if (i >= NN) return;
    int off = g_cur[i] + g_bsum[blockIdx.x];
    int deg = g_deg[i];
    float di = rsqrtf((float)deg);
    g_cur[i] = off;
    g_nd[i]  = make_int4(x[i], __float_as_int(di), off, deg - 1);
}

// EW = emb @ W1 : one block per emb row, emb row staged in smem
__global__ void k_ew(const float* __restrict__ emb, const float* __restrict__ W1) {
    __shared__ float row[DM];
    int r = blockIdx.x, c = threadIdx.x;
    row[c] = emb[r * DM + c];
    __syncthreads();
    float acc = 0.f;
#pragma unroll 8
    for (int k = 0; k < DM; k++) acc += row[k] * W1[k * DM + c];
    g_EW[r * DM + c] = acc;
}

// place edges into CSR slots (single 16B record); flag srcs of masked dsts
__global__ void k_place(const int* __restrict__ ei) {
    int e = blockIdx.x * blockDim.x + threadIdx.x;
    if (e >= NE) return;
    int s = ei[e];
    int d = ei[NE + e];
    int4 ns = g_nd[s];                       // one scattered 16B load: x[s], dinv[s]
    float dinv_d = __int_as_float(g_nd[d].y);
    float coef = __int_as_float(ns.y) * dinv_d;
    int slot = atomicAdd(&g_cur[d], 1);
    g_edge[slot] = make_int4(ns.x, s, __float_as_int(coef), 0);
    if (g_masked[d]) g_needed[s] = 1;
}

// layer-1 gather: out1[i] = b1 + dinv[i]^2*EW[x[i]] + sum coef*EW[x[src]]
// 64 threads per node (R3-proven layout), float4 per thread,
// single broadcast LDG.128 per edge for the record, unroll 2 for MLP.
__global__ void k_gather1(const float* __restrict__ b1) {
    int node = blockIdx.x * 4 + (threadIdx.x >> 6);
    if (node >= NN) return;
    if (!g_needed[node]) return;                    // uniform per 64-thread group
    int q = threadIdx.x & 63;

    const float4* EW4 = reinterpret_cast<const float4*>(g_EW);
    int4  nd = g_nd[node];
    float di = __int_as_float(nd.y);
    float dd = di * di;

    float4 w0 = EW4[nd.x * 64 + q];
    float4 bb = reinterpret_cast<const float4*>(b1)[q];
    float4 acc = make_float4(bb.x + dd * w0.x, bb.y + dd * w0.y,
                             bb.z + dd * w0.z, bb.w + dd * w0.w);

    int beg = nd.z;
    int end = beg + nd.w;
#pragma unroll 2
    for (int k = beg; k < end; k++) {
        int4 rec = g_edge[k];                       // broadcast (1 wavefront)
        float c = __int_as_float(rec.z);
        float4 w = EW4[rec.x * 64 + q];
        acc.x += c * w.x; acc.y += c * w.y; acc.z += c * w.z; acc.w += c * w.w;
    }
    reinterpret_cast<float4*>(g_out1)[node * 64 + q] = acc;
}

// layer-2 gather for masked entries only (compact j-indexed output):
//   aggc[j] = dinv^2*relu(out1[node]) + sum coef*relu(out1[src])
__global__ void k_gather2(const int* __restrict__ mask) {
    int gid = blockIdx.x * blockDim.x + threadIdx.x;
    int j = gid >> 6;
    if (j >= NM) return;
    int q = gid & 63;
    int node = mask[j];

    const float4* O4 = reinterpret_cast<const float4*>(g_out1);
    int4  nd = g_nd[node];
    float di = __int_as_float(nd.y);
    float dd = di * di;

    float4 h = O4[node * 64 + q];
    float4 acc = make_float4(dd * fmaxf(h.x, 0.f), dd * fmaxf(h.y, 0.f),
                             dd * fmaxf(h.z, 0.f), dd * fmaxf(h.w, 0.f));

    int beg = nd.z;
    int end = beg + nd.w;
#pragma unroll 2
    for (int k = beg; k < end; k++) {
        int4 rec = g_edge[k];
        float c = __int_as_float(rec.z);
        float4 hs = O4[rec.y * 64 + q];
        acc.x += c * fmaxf(hs.x, 0.f); acc.y += c * fmaxf(hs.y, 0.f);
        acc.z += c * fmaxf(hs.z, 0.f); acc.w += c * fmaxf(hs.w, 0.f);
    }
    reinterpret_cast<float4*>(g_aggc)[j * 64 + q] = acc;
}

// final: out[j] = log_softmax(aggc[j] @ W2 + b2), 32 rows per block (tail guarded)
#define FROWS 32
__global__ void __launch_bounds__(DM) k_final(const float* __restrict__ W2,
                                              const float* __restrict__ b2,
                                              float* __restrict__ out) {
    __shared__ float A[FROWS * DM];
    __shared__ float red[8];
    int c  = threadIdx.x;
    int j0 = blockIdx.x * FROWS;
    int nr = NM - j0; if (nr > FROWS) nr = FROWS;

#pragma unroll
    for (int r = 0; r < FROWS; r++)
        A[r * DM + c] = (r < nr) ? g_aggc[(j0 + r) * DM + c] : 0.f;
    __syncthreads();

    float bc = b2[c];
    float acc[FROWS];
#pragma unroll
    for (int r = 0; r < FROWS; r++) acc[r] = bc;

    const float4* A4 = reinterpret_cast<const float4*>(A);
#pragma unroll 2
    for (int kk = 0; kk < DM / 4; kk++) {
        float w0 = W2[(4 * kk + 0) * DM + c];
        float w1 = W2[(4 * kk + 1) * DM + c];
        float w2 = W2[(4 * kk + 2) * DM + c];
        float w3 = W2[(4 * kk + 3) * DM + c];
#pragma unroll
        for (int r = 0; r < FROWS; r++) {
            float4 a = A4[r * (DM / 4) + kk];
            acc[r] += a.x * w0 + a.y * w1 + a.z * w2 + a.w * w3;
        }
    }

    int lane = c & 31, wid = c >> 5;
#pragma unroll 1
    for (int r = 0; r < FROWS; r++) {
        if (r >= nr) break;                         // uniform across block
        float v = acc[r];
#pragma unroll
        for (int o = 16; o; o >>= 1) v = fmaxf(v, __shfl_xor_sync(0xffffffffu, v, o));
        if (lane == 0) red[wid] = v;
        __syncthreads();
        float m = red[0];
#pragma unroll
        for (int w = 1; w < 8; w++) m = fmaxf(m, red[w]);
        __syncthreads();
        float s = __expf(acc[r] - m);
#pragma unroll
        for (int o = 16; o; o >>= 1) s += __shfl_xor_sync(0xffffffffu, s, o);
        if (lane == 0) red[wid] = s;
        __syncthreads();
        float tot = red[0];
#pragma unroll
        for (int w = 1; w < 8; w++) tot += red[w];
        __syncthreads();
        out[(j0 + r) * DM + c] = acc[r] - m - logf(tot);
    }
}

// ---------------- launch -----------------------------------------------------
extern "C" void kernel_launch(void* const* d_in, const int* in_sizes, int n_in,
                              void* d_out, int out_size) {
    const int*   x    = (const int*)d_in[0];   // (100000,1) int32
    const int*   ei   = (const int*)d_in[1];   // (2,800000) int32: [src | dst]
    const int*   mask = (const int*)d_in[2];   // (10000,)   int32
    const float* emb  = (const float*)d_in[3]; // (256,256)
    const float* W1   = (const float*)d_in[4]; // (256,256)
    const float* b1   = (const float*)d_in[5]; // (256,)
    const float* W2   = (const float*)d_in[6]; // (256,256)
    const float* b2   = (const float*)d_in[7]; // (256,)
    float* out = (float*)d_out;                // (10000,256)

    (void)in_sizes; (void)n_in; (void)out_size;

    k_init   <<<(NN + 255) / 256, 256>>>();
    k_degmark<<<(NE + NM + 255) / 256, 256>>>(ei, mask);
    k_scanA  <<<NSB, SB>>>();
    k_scanB  <<<1, 256>>>();
    k_scanC  <<<NSB, SB>>>(x);
    k_ew     <<<VC, DM>>>(emb, W1);
    k_place  <<<(NE + 255) / 256, 256>>>(ei);
    k_gather1<<<(NN + 3) / 4, 256>>>(b1);
    k_gather2<<<(NM * 64 + 255) / 256, 256>>>(mask);
    k_final  <<<(NM + FROWS - 1) / FROWS, DM>>>(W2, b2, out);
}

// round 8
// speedup vs baseline: 1.2507x; 1.2507x over previous
#include <cuda_runtime.h>

// Problem constants (fixed shapes for this problem instance)
#define NN 100000   // nodes
#define NE 800000   // edges
#define VC 256      // vocab
#define DM 256      // node dim == hidden == vocab
#define NM 10000    // masked outputs

#define SB 512
#define NSB ((NN + SB - 1) / SB)   // 196 scan blocks

// ---------------- scratch (device globals; no allocation allowed) ----------
__device__ int   g_deg[NN];
__device__ int   g_cur[NN];
__device__ int   g_off[NN];
__device__ int   g_bsum[NSB];
__device__ float g_dinv[NN];
__device__ int   g_masked[NN];
__device__ int   g_needed[NN];
__device__ __align__(16) float g_EW[VC * DM];      // emb @ W1 (256 KB)
__device__ __align__(16) float g_out1[NN * DM];    // layer-1 pre-activation (102 MB)
__device__ __align__(16) float g_aggc[NM * DM];    // layer-2 aggregate, compact (10 MB)
// CSR payload (incoming edges grouped by dst) — R3-proven scalar arrays
__device__ int   g_ex[NE];      // x[src]
__device__ int   g_esrc[NE];    // src node
__device__ float g_ecoef[NE];   // dinv[src]*dinv[dst]

// ---------------- kernels ---------------------------------------------------
// launch index 0
__global__ void k_init(void) {
    int i = blockIdx.x * blockDim.x + threadIdx.x;
    if (i < NN) { g_deg[i] = 1; g_cur[i] = 0; g_masked[i] = 0; g_needed[i] = 0; }
}

// launch index 1: degree count (first NE threads) + mask marking (next NM)
__global__ void k_degmark(const int* __restrict__ ei, const int* __restrict__ mask) {
    int t = blockIdx.x * blockDim.x + threadIdx.x;
    if (t < NE) {
        atomicAdd(&g_deg[ei[NE + t]], 1);
    } else if (t < NE + NM) {
        int n = mask[t - NE];
        g_masked[n] = 1;
        g_needed[n] = 1;          // self term of layer-2 reads out1[node]
    }
}

// launch index 2: blocks [0,NSB) = scanA; blocks [NSB, NSB+VC) = EW gemm row
__global__ void k_scanAew(const float* __restrict__ emb, const float* __restrict__ W1) {
    __shared__ float sf[SB];
    if (blockIdx.x < NSB) {
        // ---- scanA: per-block exclusive scan of (deg-1) ----
        int* s = reinterpret_cast<int*>(sf);
        int i = blockIdx.x * SB + threadIdx.x;
        int v = (i < NN) ? (g_deg[i] - 1) : 0;
        s[threadIdx.x] = v;
        __syncthreads();
        for (int o = 1; o < SB; o <<= 1) {
            int t = (threadIdx.x >= o) ? s[threadIdx.x - o] : 0;
            __syncthreads();
            s[threadIdx.x] += t;
            __syncthreads();
        }
        int inc = s[threadIdx.x];
        if (i < NN) g_off[i] = inc - v;             // exclusive (pre-bsum)
        if (threadIdx.x == SB - 1) g_bsum[blockIdx.x] = inc;
    } else {
        // ---- EW row: g_EW[r] = emb[r] @ W1 (first DM threads active) ----
        int r = blockIdx.x - NSB;
        int c = threadIdx.x;
        if (c < DM) sf[c] = emb[r * DM + c];
        __syncthreads();
        if (c >= DM) return;
        float acc = 0.f;
#pragma unroll 8
        for (int k = 0; k < DM; k++) acc += sf[k] * W1[k * DM + c];
        g_EW[r * DM + c] = acc;
    }
}

// launch index 3: fused scanB+scanC+dinv.
// Each block redundantly scans the NSB block sums in smem, applies its own
// exclusive prefix to its 512 offsets, and computes dinv.
__global__ void k_scanBC(void) {
    __shared__ int s[256];
    int t = threadIdx.x;
    if (t < 256) {
        int v = (t < NSB) ? g_bsum[t] : 0;
        s[t] = v;
    }
    __syncthreads();
    for (int o = 1; o < 256; o <<= 1) {
        int u = 0;
        if (t < 256 && t >= o) u = s[t - o];
        __syncthreads();
        if (t < 256) s[t] += u;
        __syncthreads();
    }
    // exclusive prefix for this block
    int pre = (blockIdx.x == 0) ? 0 : s[blockIdx.x - 1];
    int i = blockIdx.x * SB + t;
    if (i < NN) {
        g_off[i] += pre;
        g_dinv[i] = rsqrtf((float)g_deg[i]);
    }
}

// launch index 4: place edges into CSR slots; flag srcs of masked dsts
__global__ void k_place(const int* __restrict__ ei, const int* __restrict__ x) {
    int e = blockIdx.x * blockDim.x + threadIdx.x;
    if (e >= NE) return;
    int s = ei[e];
    int d = ei[NE + e];
    float coef = g_dinv[s] * g_dinv[d];
    int slot = g_off[d] + atomicAdd(&g_cur[d], 1);
    g_ex[slot]    = x[s];
    g_esrc[slot]  = s;
    g_ecoef[slot] = coef;
    if (g_masked[d]) g_needed[s] = 1;
}

// launch index 5 (ncu profile target):
// layer-1 gather: out1[i] = b1 + dinv[i]^2*EW[x[i]] + sum coef*EW[x[src]]
// 64 threads per node, float4 per thread; plain coalesced store, no atomics
__global__ void k_gather1(const int* __restrict__ x, const float* __restrict__ b1) {
    int node = blockIdx.x * 4 + (threadIdx.x >> 6);
    if (node >= NN) return;
    if (!g_needed[node]) return;                    // uniform per 64-thread group
    int q = threadIdx.x & 63;

    const float4* EW4 = reinterpret_cast<const float4*>(g_EW);
    float di = g_dinv[node];
    float4 w0 = EW4[x[node] * 64 + q];
    float4 bb = reinterpret_cast<const float4*>(b1)[q];
    float dd = di * di;
    float4 acc = make_float4(bb.x + dd * w0.x, bb.y + dd * w0.y,
                             bb.z + dd * w0.z, bb.w + dd * w0.w);

    int beg = g_off[node];
    int end = beg + g_deg[node] - 1;
    for (int k = beg; k < end; k++) {
        int   xs = g_ex[k];
        float c  = g_ecoef[k];
        float4 w = EW4[xs * 64 + q];
        acc.x += c * w.x; acc.y += c * w.y; acc.z += c * w.z; acc.w += c * w.w;
    }
    reinterpret_cast<float4*>(g_out1)[node * 64 + q] = acc;
}

// launch index 6: layer-2 gather for masked entries only (compact output):
//   aggc[j] = dinv^2*relu(out1[node]) + sum coef*relu(out1[src])
__global__ void k_gather2(const int* __restrict__ mask) {
    int gid = blockIdx.x * blockDim.x + threadIdx.x;
    int j = gid >> 6;
    if (j >= NM) return;
    int q = gid & 63;
    int node = mask[j];

    const float4* O4 = reinterpret_cast<const float4*>(g_out1);
    float di = g_dinv[node];
    float dd = di * di;
    float4 h = O4[node * 64 + q];
    float4 acc = make_float4(dd * fmaxf(h.x, 0.f), dd * fmaxf(h.y, 0.f),
                             dd * fmaxf(h.z, 0.f), dd * fmaxf(h.w, 0.f));

    int beg = g_off[node];
    int end = beg + g_deg[node] - 1;
    for (int k = beg; k < end; k++) {
        int   s = g_esrc[k];
        float c = g_ecoef[k];
        float4 hs = O4[s * 64 + q];
        acc.x += c * fmaxf(hs.x, 0.f); acc.y += c * fmaxf(hs.y, 0.f);
        acc.z += c * fmaxf(hs.z, 0.f); acc.w += c * fmaxf(hs.w, 0.f);
    }
    reinterpret_cast<float4*>(g_aggc)[j * 64 + q] = acc;
}

// launch index 7: out[j] = log_softmax(aggc[j] @ W2 + b2)
// FROWS=16 (R3-proven; FROWS=32 spilled acc[] to local -> +38us, R5-R7 evidence)
#define FROWS 16
__global__ void k_final(const float* __restrict__ W2,
                        const float* __restrict__ b2,
                        float* __restrict__ out) {
    __shared__ float A[FROWS * DM];
    __shared__ float red[8];
    int c  = threadIdx.x;
    int j0 = blockIdx.x * FROWS;

#pragma unroll
    for (int r = 0; r < FROWS; r++)
        A[r * DM + c] = g_aggc[(j0 + r) * DM + c];
    __syncthreads();

    float bc = b2[c];
    float acc[FROWS];
#pragma unroll
    for (int r = 0; r < FROWS; r++) acc[r] = bc;

    const float4* A4 = reinterpret_cast<const float4*>(A);
#pragma unroll 4
    for (int kk = 0; kk < DM / 4; kk++) {
        float w0 = W2[(4 * kk + 0) * DM + c];
        float w1 = W2[(4 * kk + 1) * DM + c];
        float w2 = W2[(4 * kk + 2) * DM + c];
        float w3 = W2[(4 * kk + 3) * DM + c];
#pragma unroll
        for (int r = 0; r < FROWS; r++) {
            float4 a = A4[r * (DM / 4) + kk];
            acc[r] += a.x * w0 + a.y * w1 + a.z * w2 + a.w * w3;
        }
    }

    int lane = c & 31, wid = c >> 5;
#pragma unroll 1
    for (int r = 0; r < FROWS; r++) {
        float v = acc[r];
#pragma unroll
        for (int o = 16; o; o >>= 1) v = fmaxf(v, __shfl_xor_sync(0xffffffffu, v, o));
        if (lane == 0) red[wid] = v;
        __syncthreads();
        float m = red[0];
#pragma unroll
        for (int w = 1; w < 8; w++) m = fmaxf(m, red[w]);
        __syncthreads();
        float s = __expf(acc[r] - m);
#pragma unroll
        for (int o = 16; o; o >>= 1) s += __shfl_xor_sync(0xffffffffu, s, o);
        if (lane == 0) red[wid] = s;
        __syncthreads();
        float tot = red[0];
#pragma unroll
        for (int w = 1; w < 8; w++) tot += red[w];
        __syncthreads();
        out[(j0 + r) * DM + c] = acc[r] - m - logf(tot);
    }
}

// ---------------- launch -----------------------------------------------------
extern "C" void kernel_launch(void* const* d_in, const int* in_sizes, int n_in,
                              void* d_out, int out_size) {
    const int*   x    = (const int*)d_in[0];   // (100000,1) int32
    const int*   ei   = (const int*)d_in[1];   // (2,800000) int32: [src | dst]
    const int*   mask = (const int*)d_in[2];   // (10000,)   int32
    const float* emb  = (const float*)d_in[3]; // (256,256)
    const float* W1   = (const float*)d_in[4]; // (256,256)
    const float* b1   = (const float*)d_in[5]; // (256,)
    const float* W2   = (const float*)d_in[6]; // (256,256)
    const float* b2   = (const float*)d_in[7]; // (256,)
    float* out = (float*)d_out;                // (10000,256)

    (void)in_sizes; (void)n_in; (void)out_size;

    k_init   <<<(NN + 255) / 256, 256>>>();                    // 0
    k_degmark<<<(NE + NM + 255) / 256, 256>>>(ei, mask);       // 1
    k_scanAew<<<NSB + VC, SB>>>(emb, W1);                      // 2
    k_scanBC <<<NSB, SB>>>();                                  // 3
    k_place  <<<(NE + 255) / 256, 256>>>(ei, x);               // 4
    k_gather1<<<(NN + 3) / 4, 256>>>(x, b1);                   // 5  <- profiled
    k_gather2<<<(NM * 64 + 255) / 256, 256>>>(mask);           // 6
    k_final  <<<NM / FROWS, DM>>>(W2, b2, out);                // 7
}

// round 9
// speedup vs baseline: 1.2799x; 1.0234x over previous
#include <cuda_runtime.h>
#include <cuda_fp16.h>

// Problem constants (fixed shapes for this problem instance)
#define NN 100000   // nodes
#define NE 800000   // edges
#define VC 256      // vocab
#define DM 256      // node dim == hidden == vocab
#define NM 10000    // masked outputs

#define SB 512
#define NSB ((NN + SB - 1) / SB)   // 196 scan blocks

// ---------------- scratch (device globals; no allocation allowed) ----------
__device__ int   g_deg[NN];
__device__ int   g_cur[NN];
__device__ int   g_off[NN];
__device__ int   g_bsum[NSB];
__device__ float g_dinv[NN];
__device__ int   g_masked[NN];
__device__ int   g_needed[NN];
__device__ __align__(16) __half g_EWh[VC * DM];    // emb @ W1, fp16 (128 KB, L1-resident)
__device__ __align__(16) float g_out1[NN * DM];    // layer-1 pre-activation (102 MB)
__device__ __align__(16) float g_aggc[NM * DM];    // layer-2 aggregate, compact (10 MB)
// CSR payload (incoming edges grouped by dst) — R3-proven scalar arrays
__device__ int   g_ex[NE];      // x[src]
__device__ int   g_esrc[NE];    // src node
__device__ float g_ecoef[NE];   // dinv[src]*dinv[dst]

// ---------------- kernels ---------------------------------------------------
__global__ void k_init(void) {
    int i = blockIdx.x * blockDim.x + threadIdx.x;
    if (i < NN) { g_deg[i] = 1; g_cur[i] = 0; g_masked[i] = 0; g_needed[i] = 0; }
}

// degree count (first NE threads) + mask marking (next NM)
__global__ void k_degmark(const int* __restrict__ ei, const int* __restrict__ mask) {
    int t = blockIdx.x * blockDim.x + threadIdx.x;
    if (t < NE) {
        atomicAdd(&g_deg[ei[NE + t]], 1);
    } else if (t < NE + NM) {
        int n = mask[t - NE];
        g_masked[n] = 1;
        g_needed[n] = 1;          // self term of layer-2 reads out1[node]
    }
}

// blocks [0,NSB) = scanA; blocks [NSB, NSB+VC) = EW gemm row (fp16 out)
__global__ void k_scanAew(const float* __restrict__ emb, const float* __restrict__ W1) {
    __shared__ float sf[SB];
    if (blockIdx.x < NSB) {
        int* s = reinterpret_cast<int*>(sf);
        int i = blockIdx.x * SB + threadIdx.x;
        int v = (i < NN) ? (g_deg[i] - 1) : 0;
        s[threadIdx.x] = v;
        __syncthreads();
        for (int o = 1; o < SB; o <<= 1) {
            int t = (threadIdx.x >= o) ? s[threadIdx.x - o] : 0;
            __syncthreads();
            s[threadIdx.x] += t;
            __syncthreads();
        }
        int inc = s[threadIdx.x];
        if (i < NN) g_off[i] = inc - v;             // exclusive (pre-bsum)
        if (threadIdx.x == SB - 1) g_bsum[blockIdx.x] = inc;
    } else {
        int r = blockIdx.x - NSB;
        int c = threadIdx.x;
        if (c < DM) sf[c] = emb[r * DM + c];
        __syncthreads();
        if (c >= DM) return;
        float acc = 0.f;
#pragma unroll 8
        for (int k = 0; k < DM; k++) acc += sf[k] * W1[k * DM + c];
        g_EWh[r * DM + c] = __float2half(acc);
    }
}

// fused scanB+scanC+dinv (each block redundantly scans the NSB block sums)
__global__ void k_scanBC(void) {
    __shared__ int s[256];
    int t = threadIdx.x;
    if (t < 256) {
        int v = (t < NSB) ? g_bsum[t] : 0;
        s[t] = v;
    }
    __syncthreads();
    for (int o = 1; o < 256; o <<= 1) {
        int u = 0;
        if (t < 256 && t >= o) u = s[t - o];
        __syncthreads();
        if (t < 256) s[t] += u;
        __syncthreads();
    }
    int pre = (blockIdx.x == 0) ? 0 : s[blockIdx.x - 1];
    int i = blockIdx.x * SB + t;
    if (i < NN) {
        g_off[i] += pre;
        g_dinv[i] = rsqrtf((float)g_deg[i]);
    }
}

// place edges into CSR slots; flag srcs of masked dsts
__global__ void k_place(const int* __restrict__ ei, const int* __restrict__ x) {
    int e = blockIdx.x * blockDim.x + threadIdx.x;
    if (e >= NE) return;
    int s = ei[e];
    int d = ei[NE + e];
    float coef = g_dinv[s] * g_dinv[d];
    int slot = g_off[d] + atomicAdd(&g_cur[d], 1);
    g_ex[slot]    = x[s];
    g_esrc[slot]  = s;
    g_ecoef[slot] = coef;
    if (g_masked[d]) g_needed[s] = 1;
}

// layer-1 gather: out1[i] = b1 + dinv[i]^2*EW[x[i]] + sum coef*EW[x[src]]
// 64 threads/node; EW fp16 (L1-resident), fp32 accumulate, fp32 out1 store.
__global__ void k_gather1(const int* __restrict__ x, const float* __restrict__ b1) {
    int node = blockIdx.x * 4 + (threadIdx.x >> 6);
    if (node >= NN) return;
    if (!g_needed[node]) return;                    // uniform per 64-thread group
    int q = threadIdx.x & 63;

    const uint2* EW2 = reinterpret_cast<const uint2*>(g_EWh);  // 4 halves/thread
    float di = g_dinv[node];
    float dd = di * di;

    uint2 w0u = EW2[x[node] * 64 + q];
    float2 f0a = __half22float2(*reinterpret_cast<__half2*>(&w0u.x));
    float2 f0b = __half22float2(*reinterpret_cast<__half2*>(&w0u.y));
    float4 bb = reinterpret_cast<const float4*>(b1)[q];
    float4 acc = make_float4(bb.x + dd * f0a.x, bb.y + dd * f0a.y,
                             bb.z + dd * f0b.x, bb.w + dd * f0b.y);

    int beg = g_off[node];
    int end = beg + g_deg[node] - 1;
    for (int k = beg; k < end; k++) {
        int   xs = g_ex[k];
        float c  = g_ecoef[k];
        uint2 wu = EW2[xs * 64 + q];                // L1 hit (128 KB working set)
        float2 fa = __half22float2(*reinterpret_cast<__half2*>(&wu.x));
        float2 fb = __half22float2(*reinterpret_cast<__half2*>(&wu.y));
        acc.x += c * fa.x; acc.y += c * fa.y;
        acc.z += c * fb.x; acc.w += c * fb.y;
    }
    reinterpret_cast<float4*>(g_out1)[node * 64 + q] = acc;
}

// layer-2 gather for masked entries only (compact output):
//   aggc[j] = dinv^2*relu(out1[node]) + sum coef*relu(out1[src])
__global__ void k_gather2(const int* __restrict__ mask) {
    int gid = blockIdx.x * blockDim.x + threadIdx.x;
    int j = gid >> 6;
    if (j >= NM) return;
    int q = gid & 63;
    int node = mask[j];

    const float4* O4 = reinterpret_cast<const float4*>(g_out1);
    float di = g_dinv[node];
    float dd = di * di;
    float4 h = O4[node * 64 + q];
    float4 acc = make_float4(dd * fmaxf(h.x, 0.f), dd * fmaxf(h.y, 0.f),
                             dd * fmaxf(h.z, 0.f), dd * fmaxf(h.w, 0.f));

    int beg = g_off[node];
    int end = beg + g_deg[node] - 1;
    for (int k = beg; k < end; k++) {
        int   s = g_esrc[k];
        float c = g_ecoef[k];
        float4 hs = O4[s * 64 + q];
        acc.x += c * fmaxf(hs.x, 0.f); acc.y += c * fmaxf(hs.y, 0.f);
        acc.z += c * fmaxf(hs.z, 0.f); acc.w += c * fmaxf(hs.w, 0.f);
    }
    reinterpret_cast<float4*>(g_aggc)[j * 64 + q] = acc;
}

// out[j] = log_softmax(aggc[j] @ W2 + b2)
// FROWS=16 (proven; FROWS=32 spills acc[] -> +40us, established R5-R8)
#define FROWS 16
__global__ void k_final(const float* __restrict__ W2,
                        const float* __restrict__ b2,
                        float* __restrict__ out) {
    __shared__ float A[FROWS * DM];
    __shared__ float red[8];
    int c  = threadIdx.x;
    int j0 = blockIdx.x * FROWS;

#pragma unroll
    for (int r = 0; r < FROWS; r++)
        A[r * DM + c] = g_aggc[(j0 + r) * DM + c];
    __syncthreads();

    float bc = b2[c];
    float acc[FROWS];
#pragma unroll
    for (int r = 0; r < FROWS; r++) acc[r] = bc;

    const float4* A4 = reinterpret_cast<const float4*>(A);
#pragma unroll 4
    for (int kk = 0; kk < DM / 4; kk++) {
        float w0 = W2[(4 * kk + 0) * DM + c];
        float w1 = W2[(4 * kk + 1) * DM + c];
        float w2 = W2[(4 * kk + 2) * DM + c];
        float w3 = W2[(4 * kk + 3) * DM + c];
#pragma unroll
        for (int r = 0; r < FROWS; r++) {
            float4 a = A4[r * (DM / 4) + kk];
            acc[r] += a.x * w0 + a.y * w1 + a.z * w2 + a.w * w3;
        }
    }

    int lane = c & 31, wid = c >> 5;
#pragma unroll 1
    for (int r = 0; r < FROWS; r++) {
        float v = acc[r];
#pragma unroll
        for (int o = 16; o; o >>= 1) v = fmaxf(v, __shfl_xor_sync(0xffffffffu, v, o));
        if (lane == 0) red[wid] = v;
        __syncthreads();
        float m = red[0];
#pragma unroll
        for (int w = 1; w < 8; w++) m = fmaxf(m, red[w]);
        __syncthreads();
        float s = __expf(acc[r] - m);
#pragma unroll
        for (int o = 16; o; o >>= 1) s += __shfl_xor_sync(0xffffffffu, s, o);
        if (lane == 0) red[wid] = s;
        __syncthreads();
        float tot = red[0];
#pragma unroll
        for (int w = 1; w < 8; w++) tot += red[w];
        __syncthreads();
        out[(j0 + r) * DM + c] = acc[r] - m - logf(tot);
    }
}

// ---------------- launch -----------------------------------------------------
extern "C" void kernel_launch(void* const* d_in, const int* in_sizes, int n_in,
                              void* d_out, int out_size) {
    const int*   x    = (const int*)d_in[0];   // (100000,1) int32
    const int*   ei   = (const int*)d_in[1];   // (2,800000) int32: [src | dst]
    const int*   mask = (const int*)d_in[2];   // (10000,)   int32
    const float* emb  = (const float*)d_in[3]; // (256,256)
    const float* W1   = (const float*)d_in[4]; // (256,256)
    const float* b1   = (const float*)d_in[5]; // (256,)
    const float* W2   = (const float*)d_in[6]; // (256,256)
    const float* b2   = (const float*)d_in[7]; // (256,)
    float* out = (float*)d_out;                // (10000,256)

    (void)in_sizes; (void)n_in; (void)out_size;

    k_init   <<<(NN + 255) / 256, 256>>>();                    // 0
    k_degmark<<<(NE + NM + 255) / 256, 256>>>(ei, mask);       // 1
    k_scanAew<<<NSB + VC, SB>>>(emb, W1);                      // 2
    k_scanBC <<<NSB, SB>>>();                                  // 3
    k_place  <<<(NE + 255) / 256, 256>>>(ei, x);               // 4
    k_gather1<<<(NN + 3) / 4, 256>>>(x, b1);                   // 5
    k_gather2<<<(NM * 64 + 255) / 256, 256>>>(mask);           // 6
    k_final  <<<NM / FROWS, DM>>>(W2, b2, out);                // 7
}

// round 10
// speedup vs baseline: 1.4733x; 1.1510x over previous
#include <cuda_runtime.h>
#include <cuda_fp16.h>

// Problem constants (fixed shapes for this problem instance)
#define NN 100000   // nodes
#define NE 800000   // edges
#define VC 256      // vocab
#define DM 256      // node dim == hidden == vocab
#define NM 10000    // masked outputs

#define SB 512
#define NSB ((NN + SB - 1) / SB)   // 196 scan blocks
#define NW2B 128                   // W2 cvt blocks (65536 elems / 512)

// ---------------- scratch (device globals; no allocation allowed) ----------
__device__ int   g_deg[NN];
__device__ int   g_cur[NN];     // seeded to CSR offset in scanBC
__device__ int   g_off[NN];
__device__ int   g_bsum[NSB];
__device__ float g_dinv[NN];
__device__ int   g_masked[NN];
__device__ int   g_needed[NN];
__device__ __align__(16) __half g_EWh[VC * DM];    // emb @ W1, fp16 (128 KB)
__device__ __align__(16) __half g_W2p[DM * VC];    // W2 fp16, k-quad packed (128 KB)
__device__ __align__(16) __half g_out1h[NN * DM];  // relu(layer-1), fp16 (51 MB)
__device__ __align__(16) float  g_aggc[NM * DM];   // layer-2 aggregate (10 MB)
__device__ __align__(16) int4   g_edge[NE];        // {x[src], src, coef_bits, 0}

// ---------------- kernels ---------------------------------------------------
__global__ void k_init(void) {
    int i = blockIdx.x * blockDim.x + threadIdx.x;
    if (i < NN) { g_deg[i] = 1; g_masked[i] = 0; g_needed[i] = 0; }
}

// degree count (first NE threads) + mask marking (next NM)
__global__ void k_degmark(const int* __restrict__ ei, const int* __restrict__ mask) {
    int t = blockIdx.x * blockDim.x + threadIdx.x;
    if (t < NE) {
        atomicAdd(&g_deg[ei[NE + t]], 1);
    } else if (t < NE + NM) {
        int n = mask[t - NE];
        g_masked[n] = 1;
        g_needed[n] = 1;          // self term of layer-2 reads out1[node]
    }
}

// blocks [0,NSB): scanA | [NSB,NSB+VC): EW row | [NSB+VC,NSB+VC+NW2B): W2 cvt
__global__ void k_scanAew(const float* __restrict__ emb, const float* __restrict__ W1,
                          const float* __restrict__ W2) {
    __shared__ float sf[SB];
    if (blockIdx.x < NSB) {
        // ---- scanA: per-block exclusive scan of (deg-1) ----
        int* s = reinterpret_cast<int*>(sf);
        int i = blockIdx.x * SB + threadIdx.x;
        int v = (i < NN) ? (g_deg[i] - 1) : 0;
        s[threadIdx.x] = v;
        __syncthreads();
        for (int o = 1; o < SB; o <<= 1) {
            int t = (threadIdx.x >= o) ? s[threadIdx.x - o] : 0;
            __syncthreads();
            s[threadIdx.x] += t;
            __syncthreads();
        }
        int inc = s[threadIdx.x];
        if (i < NN) g_off[i] = inc - v;             // exclusive (pre-bsum)
        if (threadIdx.x == SB - 1) g_bsum[blockIdx.x] = inc;
    } else if (blockIdx.x < NSB + VC) {
        // ---- EW row: g_EWh[r] = fp16(emb[r] @ W1) ----
        int r = blockIdx.x - NSB;
        int c = threadIdx.x;
        if (c < DM) sf[c] = emb[r * DM + c];
        __syncthreads();
        if (c >= DM) return;
        float acc = 0.f;
#pragma unroll 8
        for (int k = 0; k < DM; k++) acc += sf[k] * W1[k * DM + c];
        g_EWh[r * DM + c] = __float2half(acc);
    } else {
        // ---- W2 cvt + k-quad pack: W2p[(kk*256+c)*4+i] = fp16(W2[(4kk+i)*256+c])
        int o = (blockIdx.x - NSB - VC) * SB + threadIdx.x;   // 0..65535
        int i = o & 3;
        int c = (o >> 2) & (DM - 1);
        int kk = o >> 10;
        g_W2p[o] = __float2half(W2[(4 * kk + i) * DM + c]);
    }
}

// fused scanB+scanC+dinv; seeds g_cur = final offset
__global__ void k_scanBC(void) {
    __shared__ int s[256];
    int t = threadIdx.x;
    if (t < 256) {
        int v = (t < NSB) ? g_bsum[t] : 0;
        s[t] = v;
    }
    __syncthreads();
    for (int o = 1; o < 256; o <<= 1) {
        int u = 0;
        if (t < 256 && t >= o) u = s[t - o];
        __syncthreads();
        if (t < 256) s[t] += u;
        __syncthreads();
    }
    int pre = (blockIdx.x == 0) ? 0 : s[blockIdx.x - 1];
    int i = blockIdx.x * SB + t;
    if (i < NN) {
        int off = g_off[i] + pre;
        g_off[i] = off;
        g_cur[i] = off;                             // place bumps this directly
        g_dinv[i] = rsqrtf((float)g_deg[i]);
    }
}

// place edges into CSR slots (single 16B scattered store); flag needed srcs
__global__ void k_place(const int* __restrict__ ei, const int* __restrict__ x) {
    int e = blockIdx.x * blockDim.x + threadIdx.x;
    if (e >= NE) return;
    int s = ei[e];
    int d = ei[NE + e];
    float coef = g_dinv[s] * g_dinv[d];
    int slot = atomicAdd(&g_cur[d], 1);
    g_edge[slot] = make_int4(x[s], s, __float_as_int(coef), 0);
    if (g_masked[d]) g_needed[s] = 1;
}

// layer-1 gather: out1h[i] = fp16(relu(b1 + dinv^2*EW[x[i]] + sum coef*EW[x[src]]))
// 64 threads/node; EW fp16 (L1-resident), fp32 accumulate.
__global__ void k_gather1(const int* __restrict__ x, const float* __restrict__ b1) {
    int node = blockIdx.x * 4 + (threadIdx.x >> 6);
    if (node >= NN) return;
    if (!g_needed[node]) return;                    // uniform per 64-thread group
    int q = threadIdx.x & 63;

    const uint2* EW2 = reinterpret_cast<const uint2*>(g_EWh);  // 4 halves/thread
    float di = g_dinv[node];
    float dd = di * di;

    uint2 w0u = EW2[x[node] * 64 + q];
    float2 f0a = __half22float2(*reinterpret_cast<__half2*>(&w0u.x));
    float2 f0b = __half22float2(*reinterpret_cast<__half2*>(&w0u.y));
    float4 bb = reinterpret_cast<const float4*>(b1)[q];
    float4 acc = make_float4(bb.x + dd * f0a.x, bb.y + dd * f0a.y,
                             bb.z + dd * f0b.x, bb.w + dd * f0b.y);

    int beg = g_off[node];
    int end = beg + g_deg[node] - 1;
    for (int k = beg; k < end; k++) {
        int4 rec = g_edge[k];                       // broadcast LDG.128
        float c = __int_as_float(rec.z);
        uint2 wu = EW2[rec.x * 64 + q];             // L1 hit (128 KB working set)
        float2 fa = __half22float2(*reinterpret_cast<__half2*>(&wu.x));
        float2 fb = __half22float2(*reinterpret_cast<__half2*>(&wu.y));
        acc.x += c * fa.x; acc.y += c * fa.y;
        acc.z += c * fb.x; acc.w += c * fb.y;
    }
    // store relu(acc) fp16 — gather2 only ever consumes relu(out1)
    __half2 oa = __floats2half2_rn(fmaxf(acc.x, 0.f), fmaxf(acc.y, 0.f));
    __half2 ob = __floats2half2_rn(fmaxf(acc.z, 0.f), fmaxf(acc.w, 0.f));
    uint2 ou;
    ou.x = *reinterpret_cast<unsigned*>(&oa);
    ou.y = *reinterpret_cast<unsigned*>(&ob);
    reinterpret_cast<uint2*>(g_out1h)[node * 64 + q] = ou;
}

// layer-2 gather, masked entries only (compact j-indexed output):
//   aggc[j] = dinv^2*h1[node] + sum coef*h1[src]   (h1 already relu'd)
__global__ void k_gather2(const int* __restrict__ mask) {
    int gid = blockIdx.x * blockDim.x + threadIdx.x;
    int j = gid >> 6;
    if (j >= NM) return;
    int q = gid & 63;
    int node = mask[j];

    const uint2* O2 = reinterpret_cast<const uint2*>(g_out1h);
    float di = g_dinv[node];
    float dd = di * di;

    uint2 hu = O2[node * 64 + q];
    float2 ha = __half22float2(*reinterpret_cast<__half2*>(&hu.x));
    float2 hb = __half22float2(*reinterpret_cast<__half2*>(&hu.y));
    float4 acc = make_float4(dd * ha.x, dd * ha.y, dd * hb.x, dd * hb.y);

    int beg = g_off[node];
    int end = beg + g_deg[node] - 1;
    for (int k = beg; k < end; k++) {
        int4 rec = g_edge[k];
        float c = __int_as_float(rec.z);
        uint2 su = O2[rec.y * 64 + q];              // 512B scattered row (was 1KB)
        float2 sa = __half22float2(*reinterpret_cast<__half2*>(&su.x));
        float2 sb = __half22float2(*reinterpret_cast<__half2*>(&su.y));
        acc.x += c * sa.x; acc.y += c * sa.y;
        acc.z += c * sb.x; acc.w += c * sb.y;
    }
    reinterpret_cast<float4*>(g_aggc)[j * 64 + q] = acc;
}

// out[j] = log_softmax(aggc[j] @ W2 + b2); W2 fp16 k-quad packed, L1-resident.
// FROWS=16 (FROWS=32 spills acc[] -> +40us, established R5-R8)
#define FROWS 16
__global__ void k_final(const float* __restrict__ b2, float* __restrict__ out) {
    __shared__ float A[FROWS * DM];
    __shared__ float red[8];
    int c  = threadIdx.x;
    int j0 = blockIdx.x * FROWS;

#pragma unroll
    for (int r = 0; r < FROWS; r++)
        A[r * DM + c] = g_aggc[(j0 + r) * DM + c];
    __syncthreads();

    float bc = b2[c];
    float acc[FROWS];
#pragma unroll
    for (int r = 0; r < FROWS; r++) acc[r] = bc;

    const float4* A4 = reinterpret_cast<const float4*>(A);
    const uint2* W2p2 = reinterpret_cast<const uint2*>(g_W2p);
#pragma unroll 4
    for (int kk = 0; kk < DM / 4; kk++) {
        uint2 wu = W2p2[kk * DM + c];               // 4 halves: k=4kk..4kk+3, col c
        float2 w01 = __half22float2(*reinterpret_cast<__half2*>(&wu.x));
        float2 w23 = __half22float2(*reinterpret_cast<__half2*>(&wu.y));
#pragma unroll
        for (int r = 0; r < FROWS; r++) {
            float4 a = A4[r * (DM / 4) + kk];
            acc[r] += a.x * w01.x + a.y * w01.y + a.z * w23.x + a.w * w23.y;
        }
    }

    int lane = c & 31, wid = c >> 5;
#pragma unroll 1
    for (int r = 0; r < FROWS; r++) {
        float v = acc[r];
#pragma unroll
        for (int o = 16; o; o >>= 1) v = fmaxf(v, __shfl_xor_sync(0xffffffffu, v, o));
        if (lane == 0) red[wid] = v;
        __syncthreads();
        float m = red[0];
#pragma unroll
        for (int w = 1; w < 8; w++) m = fmaxf(m, red[w]);
        __syncthreads();
        float s = __expf(acc[r] - m);
#pragma unroll
        for (int o = 16; o; o >>= 1) s += __shfl_xor_sync(0xffffffffu, s, o);
        if (lane == 0) red[wid] = s;
        __syncthreads();
        float tot = red[0];
#pragma unroll
        for (int w = 1; w < 8; w++) tot += red[w];
        __syncthreads();
        out[(j0 + r) * DM + c] = acc[r] - m - logf(tot);
    }
}

// ---------------- launch -----------------------------------------------------
extern "C" void kernel_launch(void* const* d_in, const int* in_sizes, int n_in,
                              void* d_out, int out_size) {
    const int*   x    = (const int*)d_in[0];   // (100000,1) int32
    const int*   ei   = (const int*)d_in[1];   // (2,800000) int32: [src | dst]
    const int*   mask = (const int*)d_in[2];   // (10000,)   int32
    const float* emb  = (const float*)d_in[3]; // (256,256)
    const float* W1   = (const float*)d_in[4]; // (256,256)
    const float* b1   = (const float*)d_in[5]; // (256,)
    const float* W2   = (const float*)d_in[6]; // (256,256)
    const float* b2   = (const float*)d_in[7]; // (256,)
    float* out = (float*)d_out;                // (10000,256)

    (void)in_sizes; (void)n_in; (void)out_size;

    k_init   <<<(NN + 255) / 256, 256>>>();                    // 0
    k_degmark<<<(NE + NM + 255) / 256, 256>>>(ei, mask);       // 1
    k_scanAew<<<NSB + VC + NW2B, SB>>>(emb, W1, W2);           // 2
    k_scanBC <<<NSB, SB>>>();                                  // 3
    k_place  <<<(NE + 255) / 256, 256>>>(ei, x);               // 4
    k_gather1<<<(NN + 3) / 4, 256>>>(x, b1);                   // 5
    k_gather2<<<(NM * 64 + 255) / 256, 256>>>(mask);           // 6
    k_final  <<<NM / FROWS, DM>>>(b2, out);                    // 7
}

// round 11
// speedup vs baseline: 1.4932x; 1.0135x over previous
#include <cuda_runtime.h>
#include <cuda_fp16.h>

// Problem constants (fixed shapes for this problem instance)
#define NN 100000   // nodes
#define NE 800000   // edges
#define VC 256      // vocab
#define DM 256      // node dim == hidden == vocab
#define NM 10000    // masked outputs

#define SB 512
#define NSB ((NN + SB - 1) / SB)   // 196 scan blocks
#define NW2B 128                   // W2 cvt blocks (65536 elems / 512)

// ---------------- scratch (device globals; no allocation allowed) ----------
__device__ int   g_deg[NN];
__device__ int   g_cur[NN];     // seeded to CSR offset in scanBC
__device__ int   g_off[NN];
__device__ int   g_bsum[NSB];
__device__ float g_dinv[NN];
__device__ int   g_masked[NN];
__device__ int   g_needed[NN];
__device__ __align__(8)  int2   g_nv[NN];          // {x | masked<<31, dinv_bits}
__device__ __align__(16) __half g_EWh[VC * DM];    // emb @ W1, fp16 (128 KB)
__device__ __align__(16) __half g_W2p[DM * VC];    // W2 fp16, k-quad packed (128 KB)
__device__ __align__(16) __half g_out1h[NN * DM];  // relu(layer-1), fp16 (51 MB)
__device__ __align__(16) float  g_aggc[NM * DM];   // layer-2 aggregate (10 MB)
__device__ __align__(16) int4   g_edge[NE];        // {x[src], src, coef_bits, 0}

// ---------------- kernels ---------------------------------------------------
__global__ void k_init(void) {
    int i = blockIdx.x * blockDim.x + threadIdx.x;
    if (i < NN) { g_deg[i] = 1; g_masked[i] = 0; g_needed[i] = 0; }
}

// degree count (first NE threads) + mask marking (next NM)
__global__ void k_degmark(const int* __restrict__ ei, const int* __restrict__ mask) {
    int t = blockIdx.x * blockDim.x + threadIdx.x;
    if (t < NE) {
        atomicAdd(&g_deg[ei[NE + t]], 1);
    } else if (t < NE + NM) {
        int n = mask[t - NE];
        g_masked[n] = 1;
        g_needed[n] = 1;          // self term of layer-2 reads out1[node]
    }
}

// blocks [0,NSB): scanA | [NSB,NSB+VC): EW row | [NSB+VC,NSB+VC+NW2B): W2 cvt
__global__ void k_scanAew(const float* __restrict__ emb, const float* __restrict__ W1,
                          const float* __restrict__ W2) {
    __shared__ float sf[SB];
    if (blockIdx.x < NSB) {
        // ---- scanA: per-block exclusive scan of (deg-1) ----
        int* s = reinterpret_cast<int*>(sf);
        int i = blockIdx.x * SB + threadIdx.x;
        int v = (i < NN) ? (g_deg[i] - 1) : 0;
        s[threadIdx.x] = v;
        __syncthreads();
        for (int o = 1; o < SB; o <<= 1) {
            int t = (threadIdx.x >= o) ? s[threadIdx.x - o] : 0;
            __syncthreads();
            s[threadIdx.x] += t;
            __syncthreads();
        }
        int inc = s[threadIdx.x];
        if (i < NN) g_off[i] = inc - v;             // exclusive (pre-bsum)
        if (threadIdx.x == SB - 1) g_bsum[blockIdx.x] = inc;
    } else if (blockIdx.x < NSB + VC) {
        // ---- EW row: g_EWh[r] = fp16(emb[r] @ W1) ----
        int r = blockIdx.x - NSB;
        int c = threadIdx.x;
        if (c < DM) sf[c] = emb[r * DM + c];
        __syncthreads();
        if (c >= DM) return;
        float acc = 0.f;
#pragma unroll 8
        for (int k = 0; k < DM; k++) acc += sf[k] * W1[k * DM + c];
        g_EWh[r * DM + c] = __float2half(acc);
    } else {
        // ---- W2 cvt + k-quad pack: W2p[(kk*256+c)*4+i] = fp16(W2[(4kk+i)*256+c])
        int o = (blockIdx.x - NSB - VC) * SB + threadIdx.x;   // 0..65535
        int i = o & 3;
        int c = (o >> 2) & (DM - 1);
        int kk = o >> 10;
        g_W2p[o] = __float2half(W2[(4 * kk + i) * DM + c]);
    }
}

// fused scanB+scanC+dinv; seeds g_cur = final offset; builds node record g_nv
__global__ void k_scanBC(const int* __restrict__ x) {
    __shared__ int s[256];
    int t = threadIdx.x;
    if (t < 256) {
        int v = (t < NSB) ? g_bsum[t] : 0;
        s[t] = v;
    }
    __syncthreads();
    for (int o = 1; o < 256; o <<= 1) {
        int u = 0;
        if (t < 256 && t >= o) u = s[t - o];
        __syncthreads();
        if (t < 256) s[t] += u;
        __syncthreads();
    }
    int pre = (blockIdx.x == 0) ? 0 : s[blockIdx.x - 1];
    int i = blockIdx.x * SB + t;
    if (i < NN) {
        int off = g_off[i] + pre;
        g_off[i] = off;
        g_cur[i] = off;                             // place bumps this directly
        float di = rsqrtf((float)g_deg[i]);
        g_dinv[i] = di;
        int xm = x[i] | (g_masked[i] << 31);        // x in [0,256): bit31 free
        g_nv[i] = make_int2(xm, __float_as_int(di));
    }
}

// place edges into CSR slots. Scattered accesses per edge: nv[s] 8B, nv[d] 8B,
// atomic, 16B store, rare needed store (was ~6.3 scattered ops before packing).
__global__ void k_place(const int* __restrict__ ei) {
    int e = blockIdx.x * blockDim.x + threadIdx.x;
    if (e >= NE) return;
    int s = ei[e];
    int d = ei[NE + e];
    int2 nvs = g_nv[s];
    int2 nvd = g_nv[d];
    float coef = __int_as_float(nvs.y) * __int_as_float(nvd.y);
    int slot = atomicAdd(&g_cur[d], 1);
    g_edge[slot] = make_int4(nvs.x & 0x7fffffff, s, __float_as_int(coef), 0);
    if (nvd.x < 0) g_needed[s] = 1;                 // dst is masked
}

// layer-1 gather: out1h[i] = fp16(relu(b1 + dinv^2*EW[x[i]] + sum coef*EW[x[src]]))
// 64 threads/node; EW fp16 (L1-resident), fp32 accumulate.
__global__ void k_gather1(const int* __restrict__ x, const float* __restrict__ b1) {
    int node = blockIdx.x * 4 + (threadIdx.x >> 6);
    if (node >= NN) return;
    if (!g_needed[node]) return;                    // uniform per 64-thread group
    int q = threadIdx.x & 63;

    const uint2* EW2 = reinterpret_cast<const uint2*>(g_EWh);  // 4 halves/thread
    float di = g_dinv[node];
    float dd = di * di;

    uint2 w0u = EW2[x[node] * 64 + q];
    float2 f0a = __half22float2(*reinterpret_cast<__half2*>(&w0u.x));
    float2 f0b = __half22float2(*reinterpret_cast<__half2*>(&w0u.y));
    float4 bb = reinterpret_cast<const float4*>(b1)[q];
    float4 acc = make_float4(bb.x + dd * f0a.x, bb.y + dd * f0a.y,
                             bb.z + dd * f0b.x, bb.w + dd * f0b.y);

    int beg = g_off[node];
    int end = beg + g_deg[node] - 1;
    for (int k = beg; k < end; k++) {
        int4 rec = g_edge[k];                       // broadcast LDG.128
        float c = __int_as_float(rec.z);
        uint2 wu = EW2[rec.x * 64 + q];             // L1 hit (128 KB working set)
        float2 fa = __half22float2(*reinterpret_cast<__half2*>(&wu.x));
        float2 fb = __half22float2(*reinterpret_cast<__half2*>(&wu.y));
        acc.x += c * fa.x; acc.y += c * fa.y;
        acc.z += c * fb.x; acc.w += c * fb.y;
    }
    // store relu(acc) fp16 — gather2 only ever consumes relu(out1)
    __half2 oa = __floats2half2_rn(fmaxf(acc.x, 0.f), fmaxf(acc.y, 0.f));
    __half2 ob = __floats2half2_rn(fmaxf(acc.z, 0.f), fmaxf(acc.w, 0.f));
    uint2 ou;
    ou.x = *reinterpret_cast<unsigned*>(&oa);
    ou.y = *reinterpret_cast<unsigned*>(&ob);
    reinterpret_cast<uint2*>(g_out1h)[node * 64 + q] = ou;
}

// layer-2 gather, masked entries only (compact j-indexed output):
//   aggc[j] = dinv^2*h1[node] + sum coef*h1[src]   (h1 already relu'd)
__global__ void k_gather2(const int* __restrict__ mask) {
    int gid = blockIdx.x * blockDim.x + threadIdx.x;
    int j = gid >> 6;
    if (j >= NM) return;
    int q = gid & 63;
    int node = mask[j];

    const uint2* O2 = reinterpret_cast<const uint2*>(g_out1h);
    float di = g_dinv[node];
    float dd = di * di;

    uint2 hu = O2[node * 64 + q];
    float2 ha = __half22float2(*reinterpret_cast<__half2*>(&hu.x));
    float2 hb = __half22float2(*reinterpret_cast<__half2*>(&hu.y));
    float4 acc = make_float4(dd * ha.x, dd * ha.y, dd * hb.x, dd * hb.y);

    int beg = g_off[node];
    int end = beg + g_deg[node] - 1;
    for (int k = beg; k < end; k++) {
        int4 rec = g_edge[k];
        float c = __int_as_float(rec.z);
        uint2 su = O2[rec.y * 64 + q];              // 512B scattered row
        float2 sa = __half22float2(*reinterpret_cast<__half2*>(&su.x));
        float2 sb = __half22float2(*reinterpret_cast<__half2*>(&su.y));
        acc.x += c * sa.x; acc.y += c * sa.y;
        acc.z += c * sb.x; acc.w += c * sb.y;
    }
    reinterpret_cast<float4*>(g_aggc)[j * 64 + q] = acc;
}

// out[j] = log_softmax(aggc[j] @ W2 + b2); W2 fp16 k-quad packed, L1-resident.
// Inner loop uses packed fma.rn.f32x2 (FFMA2): acc[r] kept as {lo,hi} partial
// sums in one b64, combined at the end. Halves FFMA issue count.
// FROWS=16 (FROWS=32 spills acc[] -> +40us, established R5-R8)
#define FROWS 16
__global__ void k_final(const float* __restrict__ b2, float* __restrict__ out) {
    __shared__ float A[FROWS * DM];
    __shared__ float red[8];
    int c  = threadIdx.x;
    int j0 = blockIdx.x * FROWS;

#pragma unroll
    for (int r = 0; r < FROWS; r++)
        A[r * DM + c] = g_aggc[(j0 + r) * DM + c];
    __syncthreads();

    float bc = b2[c];
    unsigned long long acc2[FROWS];
    unsigned long long bcpk;
    asm("mov.b64 %0, {%1, %2};" : "=l"(bcpk) : "f"(bc), "f"(0.f));
#pragma unroll
    for (int r = 0; r < FROWS; r++) acc2[r] = bcpk;

    const ulonglong2* A8 = reinterpret_cast<const ulonglong2*>(A);  // {f0,f1},{f2,f3}
    const uint2* W2p2 = reinterpret_cast<const uint2*>(g_W2p);
#pragma unroll 4
    for (int kk = 0; kk < DM / 4; kk++) {
        uint2 wu = W2p2[kk * DM + c];               // 4 halves: k=4kk..4kk+3, col c
        float2 w01 = __half22float2(*reinterpret_cast<__half2*>(&wu.x));
        float2 w23 = __half22float2(*reinterpret_cast<__half2*>(&wu.y));
        unsigned long long wp01, wp23;
        asm("mov.b64 %0, {%1, %2};" : "=l"(wp01) : "f"(w01.x), "f"(w01.y));
        asm("mov.b64 %0, {%1, %2};" : "=l"(wp23) : "f"(w23.x), "f"(w23.y));
#pragma unroll
        for (int r = 0; r < FROWS; r++) {
            ulonglong2 av = A8[r * (DM / 4) + kk];  // LDS.128 broadcast
            asm("fma.rn.f32x2 %0, %1, %2, %0;" : "+l"(acc2[r]) : "l"(av.x), "l"(wp01));
            asm("fma.rn.f32x2 %0, %1, %2, %0;" : "+l"(acc2[r]) : "l"(av.y), "l"(wp23));
        }
    }

    float acc[FROWS];
#pragma unroll
    for (int r = 0; r < FROWS; r++) {
        float lo, hi;
        asm("mov.b64 {%0, %1}, %2;" : "=f"(lo), "=f"(hi) : "l"(acc2[r]));
        acc[r] = lo + hi;
    }

    int lane = c & 31, wid = c >> 5;
#pragma unroll 1
    for (int r = 0; r < FROWS; r++) {
        float v = acc[r];
#pragma unroll
        for (int o = 16; o; o >>= 1) v = fmaxf(v, __shfl_xor_sync(0xffffffffu, v, o));
        if (lane == 0) red[wid] = v;
        __syncthreads();
        float m = red[0];
#pragma unroll
        for (int w = 1; w < 8; w++) m = fmaxf(m, red[w]);
        __syncthreads();
        float s = __expf(acc[r] - m);
#pragma unroll
        for (int o = 16; o; o >>= 1) s += __shfl_xor_sync(0xffffffffu, s, o);
        if (lane == 0) red[wid] = s;
        __syncthreads();
        float tot = red[0];
#pragma unroll
        for (int w = 1; w < 8; w++) tot += red[w];
        __syncthreads();
        out[(j0 + r) * DM + c] = acc[r] - m - logf(tot);
    }
}

// ---------------- launch -----------------------------------------------------
extern "C" void kernel_launch(void* const* d_in, const int* in_sizes, int n_in,
                              void* d_out, int out_size) {
    const int*   x    = (const int*)d_in[0];   // (100000,1) int32
    const int*   ei   = (const int*)d_in[1];   // (2,800000) int32: [src | dst]
    const int*   mask = (const int*)d_in[2];   // (10000,)   int32
    const float* emb  = (const float*)d_in[3]; // (256,256)
    const float* W1   = (const float*)d_in[4]; // (256,256)
    const float* b1   = (const float*)d_in[5]; // (256,)
    const float* W2   = (const float*)d_in[6]; // (256,256)
    const float* b2   = (const float*)d_in[7]; // (256,)
    float* out = (float*)d_out;                // (10000,256)

    (void)in_sizes; (void)n_in; (void)out_size;

    k_init   <<<(NN + 255) / 256, 256>>>();                    // 0
    k_degmark<<<(NE + NM + 255) / 256, 256>>>(ei, mask);       // 1
    k_scanAew<<<NSB + VC + NW2B, SB>>>(emb, W1, W2);           // 2
    k_scanBC <<<NSB, SB>>>(x);                                 // 3
    k_place  <<<(NE + 255) / 256, 256>>>(ei);                  // 4
    k_gather1<<<(NN + 3) / 4, 256>>>(x, b1);                   // 5
    k_gather2<<<(NM * 64 + 255) / 256, 256>>>(mask);           // 6
    k_final  <<<NM / FROWS, DM>>>(b2, out);                    // 7
}